// round 15
// baseline (speedup 1.0000x reference)
#include <cuda_runtime.h>
#include <cuda_bf16.h>
#include <math.h>
#include <stdint.h>

#define BB 8
#define CC 64
#define HH 256
#define WW 256
#define M1 20
#define M2 20
#define NL 4
#define HW 65536
#define NPIX (BB*HH*WW)

// ---------------- static device scratch ----------------
__device__ float  g_bufA[BB*CC*HW];
__device__ float  g_bufB[BB*CC*HW];
__device__ float2 g_yw [BB*CC*HH*M2];
__device__ float2 g_xft[BB*CC*2*M1*M2];
__device__ float2 g_oft[BB*CC*2*M1*M2];
__device__ float2 g_zh [BB*CC*HH*M2];
__device__ float  g_bm [NL*CC];
__device__ float  g_tc [256];
__device__ float  g_ts [256];
// bf16 hi/lo split conv weights: [l][dy][s*3+dx][n*64+ic]
__device__ __align__(16) __nv_bfloat16 g_wbf2[NL][3][6][64*64];
// bf16 hi/lo split DFT-W twiddles: [s][n(48)][k=256]
__device__ __align__(16) __nv_bfloat16 g_Tbf[2][48][256];
// pre-transposed spectral-mix weights: [l][mode][ii*64+o]
__device__ float2 g_wmix[(size_t)NL*800*4096];
// fc1 bf16 hi/lo: [s][n=128][k=64]
__device__ __align__(16) __nv_bfloat16 g_fc1bf[2][128][64];

__device__ __forceinline__ float* selbuf(int s){ return s ? g_bufB : g_bufA; }
__device__ __forceinline__ float gelu_exact(float x){
    return 0.5f * x * (1.0f + erff(x * 0.7071067811865476f));
}
__device__ __forceinline__ uint32_t bfpack(float a, float b){
    __nv_bfloat16 x = __float2bfloat16(a), y = __float2bfloat16(b);
    return (uint32_t)*(unsigned short*)&x | ((uint32_t)*(unsigned short*)&y << 16);
}
__device__ __forceinline__ void mma_bf16(float* c, const uint32_t* a, uint32_t b0, uint32_t b1){
    asm volatile("mma.sync.aligned.m16n8k16.row.col.f32.bf16.bf16.f32 "
        "{%0,%1,%2,%3}, {%4,%5,%6,%7}, {%8,%9}, {%0,%1,%2,%3};"
        : "+f"(c[0]), "+f"(c[1]), "+f"(c[2]), "+f"(c[3])
        : "r"(a[0]), "r"(a[1]), "r"(a[2]), "r"(a[3]), "r"(b0), "r"(b1));
}
#define SWZ(o) ((o) ^ (((o) >> 3) & 0x70))

// ---- smem layout: conv (64w x 64oc, swizzled 128B rows, 2 CTAs/SM) ----
#define CA_H 0                           // bf16 [198 rows][64ic] = 25344 B (reduce buf reuse)
#define CA_L 25344
#define CB_O 50688                       // bf16 [384 rows][64ic] = 49152 B
#define CSZ  99840                       // float2 [64][20] = 10240 B
#define SMEM_CONV 110080

// ---- smem layout: k_dftw_mma ----
#define DW_AH 0
#define DW_AL 67584
#define DW_BH 135168
#define DW_BL 160512
#define DW_SMEM 185856

// ---- smem layout: k_fc_mma ----
#define ICP 72
#define FA_H 0
#define FA_L 18432
#define FB_H 36864
#define FB_L 55296
#define FB1  73728
#define FW2  74240
#define FPART 74752
#define SMEM_FC 75776

// ---------------- twiddle init ----------------
__global__ void k_init_tw(){
    int i = threadIdx.x;
    const double TWO_PI = 6.283185307179586476925286766559;
    double th = TWO_PI * (double)i / 256.0;
    g_tc[i] = (float)cos(th);
    g_ts[i] = (float)sin(th);
    for (int n = 0; n < 48; n++){
        float v = 0.f;
        if (n < 20)      v =  (float)cos(TWO_PI * (double)((n*i) & 255) / 256.0);
        else if (n < 40) v = -(float)sin(TWO_PI * (double)(((n-20)*i) & 255) / 256.0);
        __nv_bfloat16 hb = __float2bfloat16(v);
        __nv_bfloat16 lb = __float2bfloat16(v - __bfloat162float(hb));
        g_Tbf[0][n][i] = hb;
        g_Tbf[1][n][i] = lb;
    }
}

// ------- merge convh+convw+pw -> bf16 hi/lo split [l][dy][s*3+dx][n][ic] -------
__global__ void k_merge(const float* __restrict__ ch, const float* __restrict__ cw,
                        const float* __restrict__ pw, const float* __restrict__ bh,
                        const float* __restrict__ bw, const float* __restrict__ bp){
    int idx = blockIdx.x * 256 + threadIdx.x;
    const int total = NL*9*64*64;
    if (idx < total){
        int ic = idx & 63;
        int n  = (idx >> 6) & 63;
        int t  = (idx >> 12) % 9;
        int l  = idx / (9*64*64);
        int dy = t / 3, dx = t % 3;
        int src = ((l*CC + n)*CC + ic)*9 + t;
        float v = ch[src] + cw[src];
        if (t == 4) v += pw[(l*CC + n)*CC + ic];
        __nv_bfloat16 hb = __float2bfloat16(v);
        __nv_bfloat16 lb = __float2bfloat16(v - __bfloat162float(hb));
        g_wbf2[l][dy][0*3+dx][n*64+ic] = hb;
        g_wbf2[l][dy][1*3+dx][n*64+ic] = lb;
    }
    if (idx < NL*CC) g_bm[idx] = bh[idx] + bw[idx] + bp[idx];
}

// ------- pre-transpose spectral weights to [l][mode][ii][o] -------
__global__ void k_wprep(const float* __restrict__ w1, const float* __restrict__ w2){
    size_t idx = (size_t)blockIdx.x * 256 + threadIdx.x;
    const size_t total = (size_t)NL*800*4096;
    if (idx >= total) return;
    int o   = idx & 63;
    int ii  = (idx >> 6) & 63;
    int ky  = (int)((idx >> 12) % 20);
    int kxi = (int)((idx / (4096ull*20)) % 40);
    int l   = (int)(idx / (4096ull*800));
    int kxl = (kxi < 20) ? kxi : kxi - 20;
    const float* w = (kxi < 20) ? w1 : w2;
    size_t s = ((((size_t)(l*64 + ii)*64 + o)*20 + kxl)*20 + ky)*2;
    g_wmix[idx] = make_float2(w[s], w[s+1]);
}

// ------- fc1 weights -> bf16 hi/lo [s][n][k] -------
__global__ void k_wprep_fc(const float* __restrict__ fc1_w){
    int idx = blockIdx.x * 256 + threadIdx.x;
    if (idx >= 128*64) return;
    int n = idx >> 6, k = idx & 63;
    float v = fc1_w[k*128 + n];
    __nv_bfloat16 hb = __float2bfloat16(v);
    __nv_bfloat16 lb = __float2bfloat16(v - __bfloat162float(hb));
    g_fc1bf[0][n][k] = hb;
    g_fc1bf[1][n][k] = lb;
}

// ---------------- fc0 lift ----------------
__global__ void k_fc0(const float* __restrict__ x, const float* __restrict__ w,
                      const float* __restrict__ bias){
    __shared__ float sw[3*CC];
    __shared__ float sb[CC];
    int tid = threadIdx.x;
    if (tid < 3*CC) sw[tid] = w[tid];
    if (tid < CC)   sb[tid] = bias[tid];
    __syncthreads();
    int pix = blockIdx.x * 256 + tid;
    int b  = pix >> 16;
    int hw = pix & 65535;
    float x0 = x[pix*3+0], x1 = x[pix*3+1], x2 = x[pix*3+2];
    float* out = selbuf(0);
    #pragma unroll 8
    for (int c = 0; c < CC; c++){
        float v = x0*sw[c] + x1*sw[64+c] + x2*sw[128+c] + sb[c];
        out[((b*CC + c) << 16) + hw] = v;
    }
}

// ============ DFT along W as tensor-core GEMM ============
__global__ void __launch_bounds__(256) k_dftw_mma(int insel){
    extern __shared__ unsigned char smem[];
    __nv_bfloat16* sAh = (__nv_bfloat16*)(smem + DW_AH);
    __nv_bfloat16* sAl = (__nv_bfloat16*)(smem + DW_AL);
    __nv_bfloat16* sBh = (__nv_bfloat16*)(smem + DW_BH);
    __nv_bfloat16* sBl = (__nv_bfloat16*)(smem + DW_BL);
    int tid = threadIdx.x, wid = tid >> 5, lane = tid & 31;
    int grp = lane >> 2, t2 = (lane & 3) * 2;
    int r0 = blockIdx.x * 128;
    const float* X = selbuf(insel) + (size_t)r0 * 256;

    for (int idx = tid; idx < 128*128; idx += 256){
        int r = idx >> 7, k2 = (idx & 127) * 2;
        float2 f = *(const float2*)&X[r*256 + k2];
        __nv_bfloat16 h0 = __float2bfloat16(f.x);
        __nv_bfloat16 h1 = __float2bfloat16(f.y);
        uint32_t hp = (uint32_t)*(unsigned short*)&h0 | ((uint32_t)*(unsigned short*)&h1 << 16);
        uint32_t lp = bfpack(f.x - __bfloat162float(h0), f.y - __bfloat162float(h1));
        *(uint32_t*)((unsigned char*)sAh + (r*264 + k2)*2) = hp;
        *(uint32_t*)((unsigned char*)sAl + (r*264 + k2)*2) = lp;
    }
    for (int idx = tid; idx < 48*128; idx += 256){
        int n = idx / 128, k2 = (idx % 128) * 2;
        *(uint32_t*)((unsigned char*)sBh + (n*264 + k2)*2) = *(const uint32_t*)&g_Tbf[0][n][k2];
        *(uint32_t*)((unsigned char*)sBl + (n*264 + k2)*2) = *(const uint32_t*)&g_Tbf[1][n][k2];
    }
    __syncthreads();

    float c[5][4];
    #pragma unroll
    for (int nb = 0; nb < 5; nb++)
        #pragma unroll
        for (int j = 0; j < 4; j++) c[nb][j] = 0.f;

    int arow = wid*16 + grp;
    #pragma unroll 4
    for (int kk = 0; kk < 16; kk++){
        int kc = kk*16 + t2;
        uint32_t ah[4], al[4];
        ah[0] = *(uint32_t*)((unsigned char*)sAh + (arow*264 + kc)*2);
        ah[1] = *(uint32_t*)((unsigned char*)sAh + ((arow+8)*264 + kc)*2);
        ah[2] = *(uint32_t*)((unsigned char*)sAh + (arow*264 + kc + 8)*2);
        ah[3] = *(uint32_t*)((unsigned char*)sAh + ((arow+8)*264 + kc + 8)*2);
        al[0] = *(uint32_t*)((unsigned char*)sAl + (arow*264 + kc)*2);
        al[1] = *(uint32_t*)((unsigned char*)sAl + ((arow+8)*264 + kc)*2);
        al[2] = *(uint32_t*)((unsigned char*)sAl + (arow*264 + kc + 8)*2);
        al[3] = *(uint32_t*)((unsigned char*)sAl + ((arow+8)*264 + kc + 8)*2);
        #pragma unroll
        for (int nb = 0; nb < 5; nb++){
            int n = nb*8 + grp;
            uint32_t bh0 = *(uint32_t*)((unsigned char*)sBh + (n*264 + kc)*2);
            uint32_t bh1 = *(uint32_t*)((unsigned char*)sBh + (n*264 + kc + 8)*2);
            uint32_t bl0 = *(uint32_t*)((unsigned char*)sBl + (n*264 + kc)*2);
            uint32_t bl1 = *(uint32_t*)((unsigned char*)sBl + (n*264 + kc + 8)*2);
            mma_bf16(c[nb], ah, bh0, bh1);
            mma_bf16(c[nb], ah, bl0, bl1);
            mma_bf16(c[nb], al, bh0, bh1);
        }
    }

    float* yw = (float*)g_yw;
    #pragma unroll
    for (int nb = 0; nb < 5; nb++){
        #pragma unroll
        for (int j = 0; j < 4; j++){
            int n = nb*8 + t2 + (j & 1);
            if (n >= 40) continue;
            int m = wid*16 + grp + ((j >> 1) << 3);
            int col = (n < 20) ? 2*n : 2*(n-20) + 1;
            yw[(size_t)(r0 + m)*40 + col] = c[nb][j];
        }
    }
}

// ---------------- forward DFT along H ----------------
__global__ void k_dfth(){
    __shared__ float2 sy[HH*M2];
    __shared__ float  stc[256], sts[256];
    int tid = threadIdx.x;          // 800
    int c = blockIdx.x, b = blockIdx.y;
    if (tid < 256){ stc[tid] = g_tc[tid]; sts[tid] = g_ts[tid]; }
    const float2* yw = g_yw + (size_t)(b*CC + c)*HH*M2;
    for (int j = tid; j < HH*M2; j += 800) sy[j] = yw[j];
    __syncthreads();
    int kxi = tid / 20, ky = tid % 20;
    int kx  = (kxi < 20) ? kxi : (216 + kxi);
    float re = 0.f, im = 0.f;
    int idx = 0;
    #pragma unroll 4
    for (int h = 0; h < HH; h++){
        float2 y = sy[h*M2 + ky];
        float cth = stc[idx], sth = sts[idx];
        re += y.x*cth + y.y*sth;
        im += y.y*cth - y.x*sth;
        idx = (idx + kx) & 255;
    }
    const float sc = 1.0f/256.0f;
    g_xft[((b*CC + c)*40 + kxi)*M2 + ky] = make_float2(re*sc, im*sc);
}

// ---------------- per-mode complex channel mixing ------------------------------
__global__ void __launch_bounds__(512) k_mix(int layer){
    __shared__ float2 sx[BB*CC];
    __shared__ float  sWr[4096], sWi[4096];
    int tid  = threadIdx.x;
    int mode = blockIdx.x;
    int kxi = mode / 20, ky = mode % 20;
    const float2* wsrc = g_wmix + ((size_t)layer*800 + mode)*4096;
    for (int j = tid; j < 4096; j += 512){
        float2 w = wsrc[j];
        sWr[j] = w.x; sWi[j] = w.y;
    }
    int b = tid >> 6, i = tid & 63;
    sx[tid] = g_xft[((b*CC + i)*40 + kxi)*M2 + ky];
    __syncthreads();
    int o = i;
    float re = 0.f, im = 0.f;
    #pragma unroll 8
    for (int ii = 0; ii < CC; ii++){
        float2 xv = sx[(b << 6) + ii];
        float wr = sWr[ii*64 + o], wi_ = sWi[ii*64 + o];
        re += xv.x*wr - xv.y*wi_;
        im += xv.x*wi_ + xv.y*wr;
    }
    g_oft[((b*CC + o)*40 + kxi)*M2 + ky] = make_float2(re, im);
}

// ---------------- inverse DFT along H (scalar) ------------------------
__global__ void k_idfth(){
    __shared__ float2 so[40*M2];
    __shared__ float  stc[256], sts[256];
    int tid = threadIdx.x;
    int o = blockIdx.x, b = blockIdx.y;
    stc[tid] = g_tc[tid]; sts[tid] = g_ts[tid];
    const float2* op = g_oft + (size_t)(b*CC + o)*40*M2;
    for (int j = tid; j < 800; j += 256) so[j] = op[j];
    __syncthreads();
    int h = tid;
    float2* zout = g_zh + ((size_t)(b*CC + o)*HH + h)*M2;
    for (int ky = 0; ky < M2; ky++){
        float re = 0.f, im = 0.f;
        #pragma unroll
        for (int kxi = 0; kxi < 40; kxi++){
            int kx  = (kxi < 20) ? kxi : (216 + kxi);
            int idx = (h * kx) & 255;
            float2 ov = so[kxi*M2 + ky];
            float cth = stc[idx], sth = sts[idx];
            re += ov.x*cth - ov.y*sth;
            im += ov.x*sth + ov.y*cth;
        }
        zout[ky] = make_float2(re, im);
    }
}

// ======== conv: 64w x 64oc x 256thr, swizzled smem, 2 CTAs/SM (R13 measured) ====
__global__ void __launch_bounds__(256) k_conv_mma(int insel, int outsel, int layer, int dogelu){
    extern __shared__ unsigned char smem[];
    float2* sz = (float2*)(smem + CSZ);

    int tid = threadIdx.x, wid = tid >> 5, lane = tid & 31;
    int w0 = blockIdx.x * 64;
    int h  = blockIdx.y;
    int b  = blockIdx.z;
    const float* in = selbuf(insel) + ((size_t)(b*CC) << 16);

    // ---- stage A: 3 dy rows x 66 w x 64 ic (hi/lo split), w lane-fast ----
    for (int idx = tid; idx < 32*198; idx += 256){
        int icp = idx / 198;            // ic pair 0..31
        int rem = idx % 198;            // dy*66 + wl
        int dy = rem / 66, wl = rem % 66;
        int gh = h + dy - 1;
        int gw = w0 - 1 + wl;
        float f0 = 0.f, f1 = 0.f;
        if (gh >= 0 && gh < HH && gw >= 0 && gw < WW){
            const float* p = in + (((size_t)(2*icp)) << 16) + gh*WW + gw;
            f0 = p[0];
            f1 = p[1 << 16];
        }
        __nv_bfloat16 h0b = __float2bfloat16(f0), h1b = __float2bfloat16(f1);
        uint32_t hp = (uint32_t)*(unsigned short*)&h0b | ((uint32_t)*(unsigned short*)&h1b << 16);
        uint32_t lp = bfpack(f0 - __bfloat162float(h0b), f1 - __bfloat162float(h1b));
        int o = rem*128 + icp*4;
        int sw = SWZ(o);
        *(uint32_t*)(smem + CA_H + sw) = hp;
        *(uint32_t*)(smem + CA_L + sw) = lp;
    }
    for (int idx = tid; idx < 64*20; idx += 256){
        int oc = idx / 20, ky = idx % 20;
        sz[idx] = g_zh[((size_t)(b*CC + oc)*HH + h)*M2 + ky];
    }

    int mq  = wid & 1;               // 32-px half
    int nh  = (wid >> 1) & 1;        // 32-oc half
    int ks  = wid >> 2;              // K half
    int grp = lane >> 2;
    int t2  = (lane & 3) * 2;

    float c[2][4][4];
    #pragma unroll
    for (int m2 = 0; m2 < 2; m2++)
        #pragma unroll
        for (int nb = 0; nb < 4; nb++)
            #pragma unroll
            for (int j = 0; j < 4; j++) c[m2][nb][j] = 0.f;

    for (int dy = 0; dy < 3; dy++){
        int gh = h + dy - 1;
        if (gh < 0 || gh >= HH) continue;
        __syncthreads();
        {   // B stage: 3072 uint4, swizzled 128B rows
            const uint4* ws = (const uint4*)&g_wbf2[layer][dy][0][0];
            for (int u = tid; u < 3072; u += 256){
                int row = u >> 3, k8 = u & 7;
                int o = row*128 + k8*16;
                *(uint4*)(smem + CB_O + SWZ(o)) = ws[u];
            }
        }
        __syncthreads();

        #pragma unroll
        for (int dx = 0; dx < 3; dx++){
            #pragma unroll
            for (int kk2 = 0; kk2 < 2; kk2++){
                int kc = (ks*2 + kk2)*16 + t2;
                uint32_t bh0[4], bh1[4], bl0[4], bl1[4];
                #pragma unroll
                for (int nb = 0; nb < 4; nb++){
                    int n = nh*32 + nb*8 + grp;
                    int bo0 = ((0*3+dx)*64 + n)*128 + kc*2;
                    int bo1 = ((1*3+dx)*64 + n)*128 + kc*2;
                    bh0[nb] = *(const uint32_t*)(smem + CB_O + SWZ(bo0));
                    bh1[nb] = *(const uint32_t*)(smem + CB_O + SWZ(bo0 + 16));
                    bl0[nb] = *(const uint32_t*)(smem + CB_O + SWZ(bo1));
                    bl1[nb] = *(const uint32_t*)(smem + CB_O + SWZ(bo1 + 16));
                }
                #pragma unroll
                for (int m2 = 0; m2 < 2; m2++){
                    int ar  = dy*66 + mq*32 + m2*16 + grp + dx;
                    int ao  = ar*128 + kc*2;
                    int ao8 = (ar+8)*128 + kc*2;
                    uint32_t ah[4], al[4];
                    ah[0] = *(const uint32_t*)(smem + CA_H + SWZ(ao));
                    ah[1] = *(const uint32_t*)(smem + CA_H + SWZ(ao8));
                    ah[2] = *(const uint32_t*)(smem + CA_H + SWZ(ao + 16));
                    ah[3] = *(const uint32_t*)(smem + CA_H + SWZ(ao8 + 16));
                    al[0] = *(const uint32_t*)(smem + CA_L + SWZ(ao));
                    al[1] = *(const uint32_t*)(smem + CA_L + SWZ(ao8));
                    al[2] = *(const uint32_t*)(smem + CA_L + SWZ(ao + 16));
                    al[3] = *(const uint32_t*)(smem + CA_L + SWZ(ao8 + 16));
                    #pragma unroll
                    for (int nb = 0; nb < 4; nb++){
                        mma_bf16(c[m2][nb], ah, bh0[nb], bh1[nb]);
                        mma_bf16(c[m2][nb], ah, bl0[nb], bl1[nb]);
                        mma_bf16(c[m2][nb], al, bh0[nb], bh1[nb]);
                    }
                }
            }
        }
        __syncthreads();
    }

    // ---- cross-K reduce via smem (reuse A region) ----
    __syncthreads();
    float* red = (float*)(smem + CA_H);
    int t = wid & 3;
    if (ks == 1){
        #pragma unroll
        for (int m2 = 0; m2 < 2; m2++)
            #pragma unroll
            for (int nb = 0; nb < 4; nb++)
                #pragma unroll
                for (int j = 0; j < 4; j++){
                    int row = m2*16 + grp + ((j >> 1) << 3);
                    int col = nb*8 + t2 + (j & 1);
                    red[t*1056 + row*33 + col] = c[m2][nb][j];
                }
    }
    __syncthreads();
    if (ks == 0){
        #pragma unroll
        for (int m2 = 0; m2 < 2; m2++)
            #pragma unroll
            for (int nb = 0; nb < 4; nb++)
                #pragma unroll
                for (int j = 0; j < 4; j++){
                    int row = m2*16 + grp + ((j >> 1) << 3);
                    int col = nb*8 + t2 + (j & 1);
                    c[m2][nb][j] += red[t*1056 + row*33 + col];
                }

        float bias[8];
        #pragma unroll
        for (int nb = 0; nb < 4; nb++){
            int oc = nh*32 + nb*8 + t2;
            bias[nb*2+0] = g_bm[layer*CC + oc];
            bias[nb*2+1] = g_bm[layer*CC + oc + 1];
        }
        float* out = selbuf(outsel) + ((size_t)(b*CC) << 16);
        #pragma unroll
        for (int m2 = 0; m2 < 2; m2++){
            #pragma unroll
            for (int jh = 0; jh < 2; jh++){
                int m  = mq*32 + m2*16 + grp + jh*8;
                int wc = w0 + m;
                float c1 = g_tc[wc], s1 = g_ts[wc];
                float acc[8];
                #pragma unroll
                for (int nb = 0; nb < 4; nb++){
                    int oc = nh*32 + nb*8 + t2;
                    acc[nb*2+0] = sz[oc*20].x;
                    acc[nb*2+1] = sz[(oc+1)*20].x;
                }
                float cr = c1, ci = s1;
                for (int ky = 1; ky < 20; ky++){
                    #pragma unroll
                    for (int nb = 0; nb < 4; nb++){
                        int oc = nh*32 + nb*8 + t2;
                        float2 z0 = sz[oc*20 + ky];
                        float2 z1 = sz[(oc+1)*20 + ky];
                        acc[nb*2+0] += 2.f*(z0.x*cr - z0.y*ci);
                        acc[nb*2+1] += 2.f*(z1.x*cr - z1.y*ci);
                    }
                    float nr = cr*c1 - ci*s1;
                    ci = cr*s1 + ci*c1;
                    cr = nr;
                }
                #pragma unroll
                for (int nb = 0; nb < 4; nb++){
                    int oc = nh*32 + nb*8 + t2;
                    #pragma unroll
                    for (int j2 = 0; j2 < 2; j2++){
                        float v = c[m2][nb][jh*2 + j2] + bias[nb*2+j2] + acc[nb*2+j2]*(1.0f/256.0f);
                        if (dogelu) v = gelu_exact(v);
                        out[((size_t)(oc + j2) << 16) + h*WW + wc] = v;
                    }
                }
            }
        }
    }
}

// ======== head via mma: fc1(64->128) GEMM + gelu + fc2 dot ========
__global__ void __launch_bounds__(512) k_fc_mma(const float* __restrict__ b1,
        const float* __restrict__ w2, const float* __restrict__ b2,
        float* __restrict__ out, int sel){
    extern __shared__ unsigned char smem[];
    __nv_bfloat16* sAh = (__nv_bfloat16*)(smem + FA_H);
    __nv_bfloat16* sAl = (__nv_bfloat16*)(smem + FA_L);
    __nv_bfloat16* sBh = (__nv_bfloat16*)(smem + FB_H);
    __nv_bfloat16* sBl = (__nv_bfloat16*)(smem + FB_L);
    float* sb1  = (float*)(smem + FB1);
    float* sw2  = (float*)(smem + FW2);
    float* part = (float*)(smem + FPART);

    int tid = threadIdx.x, wid = tid >> 5, lane = tid & 31;
    int grp = lane >> 2, t2 = (lane & 3) * 2;
    int pbase = blockIdx.x * 128;
    int b  = pbase >> 16;
    int hw0 = pbase & 65535;
    const float* hbuf = selbuf(sel);

    for (int u = tid; u < 128*32; u += 512){
        int px  = u & 127;
        int icp = u >> 7;
        const float* p = hbuf + (((size_t)(b*CC + 2*icp)) << 16) + hw0 + px;
        float f0 = p[0], f1 = p[1 << 16];
        __nv_bfloat16 h0b = __float2bfloat16(f0), h1b = __float2bfloat16(f1);
        uint32_t hp = (uint32_t)*(unsigned short*)&h0b | ((uint32_t)*(unsigned short*)&h1b << 16);
        uint32_t lp = bfpack(f0 - __bfloat162float(h0b), f1 - __bfloat162float(h1b));
        *(uint32_t*)((unsigned char*)sAh + px*144 + icp*4) = hp;
        *(uint32_t*)((unsigned char*)sAl + px*144 + icp*4) = lp;
    }
    for (int u = tid; u < 2*1024; u += 512){
        int s = u >> 10, r = u & 1023;
        int n = r >> 3, k8 = r & 7;
        uint4 v = *(const uint4*)&g_fc1bf[s][n][k8*8];
        unsigned char* dst = (s ? (unsigned char*)sBl : (unsigned char*)sBh);
        *(uint4*)(dst + n*144 + k8*16) = v;
    }
    if (tid < 128){ sb1[tid] = b1[tid]; sw2[tid] = w2[tid]; }
    __syncthreads();

    int mq = wid & 7;
    int nh = wid >> 3;
    float c[8][4];
    #pragma unroll
    for (int nb = 0; nb < 8; nb++)
        #pragma unroll
        for (int j = 0; j < 4; j++) c[nb][j] = 0.f;

    int arow = mq*16 + grp;
    #pragma unroll
    for (int kk = 0; kk < 4; kk++){
        int kc = kk*16 + t2;
        uint32_t ah[4], al[4];
        ah[0] = *(const uint32_t*)(sAh + arow*ICP + kc);
        ah[1] = *(const uint32_t*)(sAh + (arow+8)*ICP + kc);
        ah[2] = *(const uint32_t*)(sAh + arow*ICP + kc + 8);
        ah[3] = *(const uint32_t*)(sAh + (arow+8)*ICP + kc + 8);
        al[0] = *(const uint32_t*)(sAl + arow*ICP + kc);
        al[1] = *(const uint32_t*)(sAl + (arow+8)*ICP + kc);
        al[2] = *(const uint32_t*)(sAl + arow*ICP + kc + 8);
        al[3] = *(const uint32_t*)(sAl + (arow+8)*ICP + kc + 8);
        #pragma unroll
        for (int nb = 0; nb < 8; nb++){
            int n = nh*64 + nb*8 + grp;
            uint32_t bh0 = *(const uint32_t*)(sBh + n*ICP + kc);
            uint32_t bh1 = *(const uint32_t*)(sBh + n*ICP + kc + 8);
            uint32_t bl0 = *(const uint32_t*)(sBl + n*ICP + kc);
            uint32_t bl1 = *(const uint32_t*)(sBl + n*ICP + kc + 8);
            mma_bf16(c[nb], ah, bh0, bh1);
            mma_bf16(c[nb], ah, bl0, bl1);
            mma_bf16(c[nb], al, bh0, bh1);
        }
    }

    float s0 = 0.f, s1 = 0.f;
    #pragma unroll
    for (int nb = 0; nb < 8; nb++){
        int n0 = nh*64 + nb*8 + t2;
        float b10 = sb1[n0], b11 = sb1[n0+1];
        float w20 = sw2[n0], w21 = sw2[n0+1];
        s0 += gelu_exact(c[nb][0] + b10) * w20 + gelu_exact(c[nb][1] + b11) * w21;
        s1 += gelu_exact(c[nb][2] + b10) * w20 + gelu_exact(c[nb][3] + b11) * w21;
    }
    #pragma unroll
    for (int off = 1; off <= 2; off <<= 1){
        s0 += __shfl_xor_sync(0xffffffffu, s0, off);
        s1 += __shfl_xor_sync(0xffffffffu, s1, off);
    }
    if ((lane & 3) == 0){
        part[nh*128 + mq*16 + grp]     = s0;
        part[nh*128 + mq*16 + grp + 8] = s1;
    }
    __syncthreads();
    if (tid < 128) out[pbase + tid] = part[tid] + part[128 + tid] + b2[0];
}

// ---------------- launch ----------------
extern "C" void kernel_launch(void* const* d_in, const int* in_sizes, int n_in,
                              void* d_out, int out_size){
    const float* x     = (const float*)d_in[0];
    const float* fc0_w = (const float*)d_in[1];
    const float* fc0_b = (const float*)d_in[2];
    const float* w1    = (const float*)d_in[3];
    const float* w2    = (const float*)d_in[4];
    const float* chw   = (const float*)d_in[5];
    const float* chb   = (const float*)d_in[6];
    const float* cww   = (const float*)d_in[7];
    const float* cwb   = (const float*)d_in[8];
    const float* pww   = (const float*)d_in[9];
    const float* pwb   = (const float*)d_in[10];
    const float* fc1_w = (const float*)d_in[11];
    const float* fc1_b = (const float*)d_in[12];
    const float* fc2_w = (const float*)d_in[13];
    const float* fc2_b = (const float*)d_in[14];
    float* out = (float*)d_out;

    cudaFuncSetAttribute(k_conv_mma, cudaFuncAttributeMaxDynamicSharedMemorySize, SMEM_CONV);
    cudaFuncSetAttribute(k_dftw_mma, cudaFuncAttributeMaxDynamicSharedMemorySize, DW_SMEM);
    cudaFuncSetAttribute(k_fc_mma,   cudaFuncAttributeMaxDynamicSharedMemorySize, SMEM_FC);

    k_init_tw<<<1, 256>>>();
    k_merge<<<(NL*9*64*64 + 255)/256, 256>>>(chw, cww, pww, chb, cwb, pwb);
    k_wprep<<<(int)(((size_t)NL*800*4096 + 255)/256), 256>>>(w1, w2);
    k_wprep_fc<<<(128*64 + 255)/256, 256>>>(fc1_w);
    k_fc0<<<NPIX/256, 256>>>(x, fc0_w, fc0_b);

    int cur = 0;
    for (int l = 0; l < NL; l++){
        int nxt = cur ^ 1;
        k_dftw_mma<<<1024, 256, DW_SMEM>>>(cur);
        k_dfth <<<dim3(CC, BB), 800>>>();
        k_mix  <<<800, 512>>>(l);
        k_idfth<<<dim3(CC, BB), 256>>>();
        k_conv_mma<<<dim3(4, HH, BB), 256, SMEM_CONV>>>(cur, nxt, l, (l < NL-1) ? 1 : 0);
        cur = nxt;
    }
    k_fc_mma<<<NPIX/128, 512, SMEM_FC>>>(fc1_b, fc2_w, fc2_b, out, cur);
}

// round 16
// speedup vs baseline: 1.5050x; 1.5050x over previous
#include <cuda_runtime.h>
#include <cuda_bf16.h>
#include <math.h>
#include <stdint.h>

#define BB 8
#define CC 64
#define HH 256
#define WW 256
#define M1 20
#define M2 20
#define NL 4
#define HW 65536
#define NPIX (BB*HH*WW)

// ---------------- static device scratch ----------------
__device__ float  g_bufA[BB*CC*HW];
__device__ float  g_bufB[BB*CC*HW];
__device__ float2 g_yw [BB*CC*HH*M2];
__device__ float2 g_xft[BB*CC*2*M1*M2];
__device__ float2 g_oft[BB*CC*2*M1*M2];
__device__ float2 g_zh [BB*CC*HH*M2];
__device__ float  g_bm [NL*CC];
__device__ float  g_tc [256];
__device__ float  g_ts [256];
// bf16 hi/lo split conv weights: [l][dy][s*3+dx][n*64+ic]
__device__ __align__(16) __nv_bfloat16 g_wbf2[NL][3][6][64*64];
// bf16 hi/lo split DFT-W twiddles: [s][n(48)][k=256]
__device__ __align__(16) __nv_bfloat16 g_Tbf[2][48][256];
// pre-transposed spectral-mix weights: [l][mode][ii*64+o]
__device__ float2 g_wmix[(size_t)NL*800*4096];
// fc1 bf16 hi/lo: [s][n=128][k=64]
__device__ __align__(16) __nv_bfloat16 g_fc1bf[2][128][64];

__device__ __forceinline__ float* selbuf(int s){ return s ? g_bufB : g_bufA; }
__device__ __forceinline__ float gelu_exact(float x){
    return 0.5f * x * (1.0f + erff(x * 0.7071067811865476f));
}
__device__ __forceinline__ uint32_t bfpack(float a, float b){
    __nv_bfloat16 x = __float2bfloat16(a), y = __float2bfloat16(b);
    return (uint32_t)*(unsigned short*)&x | ((uint32_t)*(unsigned short*)&y << 16);
}
__device__ __forceinline__ void mma_bf16(float* c, const uint32_t* a, uint32_t b0, uint32_t b1){
    asm volatile("mma.sync.aligned.m16n8k16.row.col.f32.bf16.bf16.f32 "
        "{%0,%1,%2,%3}, {%4,%5,%6,%7}, {%8,%9}, {%0,%1,%2,%3};"
        : "+f"(c[0]), "+f"(c[1]), "+f"(c[2]), "+f"(c[3])
        : "r"(a[0]), "r"(a[1]), "r"(a[2]), "r"(a[3]), "r"(b0), "r"(b1));
}
#define SWZ(o) ((o) ^ (((o) >> 3) & 0x70))

// ---- smem layout: conv (64w x 64oc, swizzled 128B rows, 2 CTAs/SM) ----
#define CA_H 0                           // bf16 [198 rows][64ic] = 25344 B (reduce buf reuse)
#define CA_L 25344
#define CB_O 50688                       // bf16 [384 rows][64ic] = 49152 B
#define CSZ  99840                       // float2 [64][20] = 10240 B
#define SMEM_CONV 110080

// ---- smem layout: k_dftw_mma ----
#define DW_AH 0
#define DW_AL 67584
#define DW_BH 135168
#define DW_BL 160512
#define DW_SMEM 185856

// ---- smem layout: k_fc_mma ----
#define ICP 72
#define FA_H 0
#define FA_L 18432
#define FB_H 36864
#define FB_L 55296
#define FB1  73728
#define FW2  74240
#define FPART 74752
#define SMEM_FC 75776

// ---------------- twiddle init ----------------
__global__ void k_init_tw(){
    int i = threadIdx.x;
    const double TWO_PI = 6.283185307179586476925286766559;
    double th = TWO_PI * (double)i / 256.0;
    g_tc[i] = (float)cos(th);
    g_ts[i] = (float)sin(th);
    for (int n = 0; n < 48; n++){
        float v = 0.f;
        if (n < 20)      v =  (float)cos(TWO_PI * (double)((n*i) & 255) / 256.0);
        else if (n < 40) v = -(float)sin(TWO_PI * (double)(((n-20)*i) & 255) / 256.0);
        __nv_bfloat16 hb = __float2bfloat16(v);
        __nv_bfloat16 lb = __float2bfloat16(v - __bfloat162float(hb));
        g_Tbf[0][n][i] = hb;
        g_Tbf[1][n][i] = lb;
    }
}

// ------- merge convh+convw+pw -> bf16 hi/lo split [l][dy][s*3+dx][n][ic] -------
__global__ void k_merge(const float* __restrict__ ch, const float* __restrict__ cw,
                        const float* __restrict__ pw, const float* __restrict__ bh,
                        const float* __restrict__ bw, const float* __restrict__ bp){
    int idx = blockIdx.x * 256 + threadIdx.x;
    const int total = NL*9*64*64;
    if (idx < total){
        int ic = idx & 63;
        int n  = (idx >> 6) & 63;
        int t  = (idx >> 12) % 9;
        int l  = idx / (9*64*64);
        int dy = t / 3, dx = t % 3;
        int src = ((l*CC + n)*CC + ic)*9 + t;
        float v = ch[src] + cw[src];
        if (t == 4) v += pw[(l*CC + n)*CC + ic];
        __nv_bfloat16 hb = __float2bfloat16(v);
        __nv_bfloat16 lb = __float2bfloat16(v - __bfloat162float(hb));
        g_wbf2[l][dy][0*3+dx][n*64+ic] = hb;
        g_wbf2[l][dy][1*3+dx][n*64+ic] = lb;
    }
    if (idx < NL*CC) g_bm[idx] = bh[idx] + bw[idx] + bp[idx];
}

// ------- pre-transpose spectral weights to [l][mode][ii][o] -------
__global__ void k_wprep(const float* __restrict__ w1, const float* __restrict__ w2){
    size_t idx = (size_t)blockIdx.x * 256 + threadIdx.x;
    const size_t total = (size_t)NL*800*4096;
    if (idx >= total) return;
    int o   = idx & 63;
    int ii  = (idx >> 6) & 63;
    int ky  = (int)((idx >> 12) % 20);
    int kxi = (int)((idx / (4096ull*20)) % 40);
    int l   = (int)(idx / (4096ull*800));
    int kxl = (kxi < 20) ? kxi : kxi - 20;
    const float* w = (kxi < 20) ? w1 : w2;
    size_t s = ((((size_t)(l*64 + ii)*64 + o)*20 + kxl)*20 + ky)*2;
    g_wmix[idx] = make_float2(w[s], w[s+1]);
}

// ------- fc1 weights -> bf16 hi/lo [s][n][k] -------
__global__ void k_wprep_fc(const float* __restrict__ fc1_w){
    int idx = blockIdx.x * 256 + threadIdx.x;
    if (idx >= 128*64) return;
    int n = idx >> 6, k = idx & 63;
    float v = fc1_w[k*128 + n];
    __nv_bfloat16 hb = __float2bfloat16(v);
    __nv_bfloat16 lb = __float2bfloat16(v - __bfloat162float(hb));
    g_fc1bf[0][n][k] = hb;
    g_fc1bf[1][n][k] = lb;
}

// ---------------- fc0 lift ----------------
__global__ void k_fc0(const float* __restrict__ x, const float* __restrict__ w,
                      const float* __restrict__ bias){
    __shared__ float sw[3*CC];
    __shared__ float sb[CC];
    int tid = threadIdx.x;
    if (tid < 3*CC) sw[tid] = w[tid];
    if (tid < CC)   sb[tid] = bias[tid];
    __syncthreads();
    int pix = blockIdx.x * 256 + tid;
    int b  = pix >> 16;
    int hw = pix & 65535;
    float x0 = x[pix*3+0], x1 = x[pix*3+1], x2 = x[pix*3+2];
    float* out = selbuf(0);
    #pragma unroll 8
    for (int c = 0; c < CC; c++){
        float v = x0*sw[c] + x1*sw[64+c] + x2*sw[128+c] + sb[c];
        out[((b*CC + c) << 16) + hw] = v;
    }
}

// ============ DFT along W as tensor-core GEMM ============
__global__ void __launch_bounds__(256) k_dftw_mma(int insel){
    extern __shared__ unsigned char smem[];
    __nv_bfloat16* sAh = (__nv_bfloat16*)(smem + DW_AH);
    __nv_bfloat16* sAl = (__nv_bfloat16*)(smem + DW_AL);
    __nv_bfloat16* sBh = (__nv_bfloat16*)(smem + DW_BH);
    __nv_bfloat16* sBl = (__nv_bfloat16*)(smem + DW_BL);
    int tid = threadIdx.x, wid = tid >> 5, lane = tid & 31;
    int grp = lane >> 2, t2 = (lane & 3) * 2;
    int r0 = blockIdx.x * 128;
    const float* X = selbuf(insel) + (size_t)r0 * 256;

    for (int idx = tid; idx < 128*128; idx += 256){
        int r = idx >> 7, k2 = (idx & 127) * 2;
        float2 f = *(const float2*)&X[r*256 + k2];
        __nv_bfloat16 h0 = __float2bfloat16(f.x);
        __nv_bfloat16 h1 = __float2bfloat16(f.y);
        uint32_t hp = (uint32_t)*(unsigned short*)&h0 | ((uint32_t)*(unsigned short*)&h1 << 16);
        uint32_t lp = bfpack(f.x - __bfloat162float(h0), f.y - __bfloat162float(h1));
        *(uint32_t*)((unsigned char*)sAh + (r*264 + k2)*2) = hp;
        *(uint32_t*)((unsigned char*)sAl + (r*264 + k2)*2) = lp;
    }
    for (int idx = tid; idx < 48*128; idx += 256){
        int n = idx / 128, k2 = (idx % 128) * 2;
        *(uint32_t*)((unsigned char*)sBh + (n*264 + k2)*2) = *(const uint32_t*)&g_Tbf[0][n][k2];
        *(uint32_t*)((unsigned char*)sBl + (n*264 + k2)*2) = *(const uint32_t*)&g_Tbf[1][n][k2];
    }
    __syncthreads();

    float c[5][4];
    #pragma unroll
    for (int nb = 0; nb < 5; nb++)
        #pragma unroll
        for (int j = 0; j < 4; j++) c[nb][j] = 0.f;

    int arow = wid*16 + grp;
    #pragma unroll 4
    for (int kk = 0; kk < 16; kk++){
        int kc = kk*16 + t2;
        uint32_t ah[4], al[4];
        ah[0] = *(uint32_t*)((unsigned char*)sAh + (arow*264 + kc)*2);
        ah[1] = *(uint32_t*)((unsigned char*)sAh + ((arow+8)*264 + kc)*2);
        ah[2] = *(uint32_t*)((unsigned char*)sAh + (arow*264 + kc + 8)*2);
        ah[3] = *(uint32_t*)((unsigned char*)sAh + ((arow+8)*264 + kc + 8)*2);
        al[0] = *(uint32_t*)((unsigned char*)sAl + (arow*264 + kc)*2);
        al[1] = *(uint32_t*)((unsigned char*)sAl + ((arow+8)*264 + kc)*2);
        al[2] = *(uint32_t*)((unsigned char*)sAl + (arow*264 + kc + 8)*2);
        al[3] = *(uint32_t*)((unsigned char*)sAl + ((arow+8)*264 + kc + 8)*2);
        #pragma unroll
        for (int nb = 0; nb < 5; nb++){
            int n = nb*8 + grp;
            uint32_t bh0 = *(uint32_t*)((unsigned char*)sBh + (n*264 + kc)*2);
            uint32_t bh1 = *(uint32_t*)((unsigned char*)sBh + (n*264 + kc + 8)*2);
            uint32_t bl0 = *(uint32_t*)((unsigned char*)sBl + (n*264 + kc)*2);
            uint32_t bl1 = *(uint32_t*)((unsigned char*)sBl + (n*264 + kc + 8)*2);
            mma_bf16(c[nb], ah, bh0, bh1);
            mma_bf16(c[nb], ah, bl0, bl1);
            mma_bf16(c[nb], al, bh0, bh1);
        }
    }

    float* yw = (float*)g_yw;
    #pragma unroll
    for (int nb = 0; nb < 5; nb++){
        #pragma unroll
        for (int j = 0; j < 4; j++){
            int n = nb*8 + t2 + (j & 1);
            if (n >= 40) continue;
            int m = wid*16 + grp + ((j >> 1) << 3);
            int col = (n < 20) ? 2*n : 2*(n-20) + 1;
            yw[(size_t)(r0 + m)*40 + col] = c[nb][j];
        }
    }
}

// ---------------- forward DFT along H ----------------
__global__ void k_dfth(){
    __shared__ float2 sy[HH*M2];
    __shared__ float  stc[256], sts[256];
    int tid = threadIdx.x;          // 800
    int c = blockIdx.x, b = blockIdx.y;
    if (tid < 256){ stc[tid] = g_tc[tid]; sts[tid] = g_ts[tid]; }
    const float2* yw = g_yw + (size_t)(b*CC + c)*HH*M2;
    for (int j = tid; j < HH*M2; j += 800) sy[j] = yw[j];
    __syncthreads();
    int kxi = tid / 20, ky = tid % 20;
    int kx  = (kxi < 20) ? kxi : (216 + kxi);
    float re = 0.f, im = 0.f;
    int idx = 0;
    #pragma unroll 4
    for (int h = 0; h < HH; h++){
        float2 y = sy[h*M2 + ky];
        float cth = stc[idx], sth = sts[idx];
        re += y.x*cth + y.y*sth;
        im += y.y*cth - y.x*sth;
        idx = (idx + kx) & 255;
    }
    const float sc = 1.0f/256.0f;
    g_xft[((b*CC + c)*40 + kxi)*M2 + ky] = make_float2(re*sc, im*sc);
}

// ---------------- per-mode complex channel mixing ------------------------------
__global__ void __launch_bounds__(512) k_mix(int layer){
    __shared__ float2 sx[BB*CC];
    __shared__ float  sWr[4096], sWi[4096];
    int tid  = threadIdx.x;
    int mode = blockIdx.x;
    int kxi = mode / 20, ky = mode % 20;
    const float2* wsrc = g_wmix + ((size_t)layer*800 + mode)*4096;
    for (int j = tid; j < 4096; j += 512){
        float2 w = wsrc[j];
        sWr[j] = w.x; sWi[j] = w.y;
    }
    int b = tid >> 6, i = tid & 63;
    sx[tid] = g_xft[((b*CC + i)*40 + kxi)*M2 + ky];
    __syncthreads();
    int o = i;
    float re = 0.f, im = 0.f;
    #pragma unroll 8
    for (int ii = 0; ii < CC; ii++){
        float2 xv = sx[(b << 6) + ii];
        float wr = sWr[ii*64 + o], wi_ = sWi[ii*64 + o];
        re += xv.x*wr - xv.y*wi_;
        im += xv.x*wi_ + xv.y*wr;
    }
    g_oft[((b*CC + o)*40 + kxi)*M2 + ky] = make_float2(re, im);
}

// ---------------- inverse DFT along H (scalar) ------------------------
__global__ void k_idfth(){
    __shared__ float2 so[40*M2];
    __shared__ float  stc[256], sts[256];
    int tid = threadIdx.x;
    int o = blockIdx.x, b = blockIdx.y;
    stc[tid] = g_tc[tid]; sts[tid] = g_ts[tid];
    const float2* op = g_oft + (size_t)(b*CC + o)*40*M2;
    for (int j = tid; j < 800; j += 256) so[j] = op[j];
    __syncthreads();
    int h = tid;
    float2* zout = g_zh + ((size_t)(b*CC + o)*HH + h)*M2;
    for (int ky = 0; ky < M2; ky++){
        float re = 0.f, im = 0.f;
        #pragma unroll
        for (int kxi = 0; kxi < 40; kxi++){
            int kx  = (kxi < 20) ? kxi : (216 + kxi);
            int idx = (h * kx) & 255;
            float2 ov = so[kxi*M2 + ky];
            float cth = stc[idx], sth = sts[idx];
            re += ov.x*cth - ov.y*sth;
            im += ov.x*sth + ov.y*cth;
        }
        zout[ky] = make_float2(re, im);
    }
}

// ======== conv: 64w x 64oc x 256thr, swizzled smem, pinned 2 CTAs/SM ====
__global__ void __launch_bounds__(256, 2) k_conv_mma(int insel, int outsel, int layer, int dogelu){
    extern __shared__ unsigned char smem[];
    float2* sz = (float2*)(smem + CSZ);

    int tid = threadIdx.x, wid = tid >> 5, lane = tid & 31;
    int w0 = blockIdx.x * 64;
    int h  = blockIdx.y;
    int b  = blockIdx.z;
    const float* in = selbuf(insel) + ((size_t)(b*CC) << 16);

    // ---- stage A: 3 dy rows x 66 w x 64 ic (hi/lo split), w lane-fast ----
    for (int idx = tid; idx < 32*198; idx += 256){
        int icp = idx / 198;            // ic pair 0..31
        int rem = idx % 198;            // dy*66 + wl
        int dy = rem / 66, wl = rem % 66;
        int gh = h + dy - 1;
        int gw = w0 - 1 + wl;
        float f0 = 0.f, f1 = 0.f;
        if (gh >= 0 && gh < HH && gw >= 0 && gw < WW){
            const float* p = in + (((size_t)(2*icp)) << 16) + gh*WW + gw;
            f0 = p[0];
            f1 = p[1 << 16];
        }
        __nv_bfloat16 h0b = __float2bfloat16(f0), h1b = __float2bfloat16(f1);
        uint32_t hp = (uint32_t)*(unsigned short*)&h0b | ((uint32_t)*(unsigned short*)&h1b << 16);
        uint32_t lp = bfpack(f0 - __bfloat162float(h0b), f1 - __bfloat162float(h1b));
        int o = rem*128 + icp*4;
        int sw = SWZ(o);
        *(uint32_t*)(smem + CA_H + sw) = hp;
        *(uint32_t*)(smem + CA_L + sw) = lp;
    }
    for (int idx = tid; idx < 64*20; idx += 256){
        int oc = idx / 20, ky = idx % 20;
        sz[idx] = g_zh[((size_t)(b*CC + oc)*HH + h)*M2 + ky];
    }

    int mq  = wid & 1;               // 32-px half
    int nh  = (wid >> 1) & 1;        // 32-oc half
    int ks  = wid >> 2;              // K half
    int grp = lane >> 2;
    int t2  = (lane & 3) * 2;

    float c[2][4][4];
    #pragma unroll
    for (int m2 = 0; m2 < 2; m2++)
        #pragma unroll
        for (int nb = 0; nb < 4; nb++)
            #pragma unroll
            for (int j = 0; j < 4; j++) c[m2][nb][j] = 0.f;

    for (int dy = 0; dy < 3; dy++){
        int gh = h + dy - 1;
        if (gh < 0 || gh >= HH) continue;
        __syncthreads();
        {   // B stage: 3072 uint4, swizzled 128B rows
            const uint4* ws = (const uint4*)&g_wbf2[layer][dy][0][0];
            for (int u = tid; u < 3072; u += 256){
                int row = u >> 3, k8 = u & 7;
                int o = row*128 + k8*16;
                *(uint4*)(smem + CB_O + SWZ(o)) = ws[u];
            }
        }
        __syncthreads();

        #pragma unroll
        for (int dx = 0; dx < 3; dx++){
            #pragma unroll
            for (int kk2 = 0; kk2 < 2; kk2++){
                int kc = (ks*2 + kk2)*16 + t2;
                uint32_t bh0[4], bh1[4], bl0[4], bl1[4];
                #pragma unroll
                for (int nb = 0; nb < 4; nb++){
                    int n = nh*32 + nb*8 + grp;
                    int bo0 = ((0*3+dx)*64 + n)*128 + kc*2;
                    int bo1 = ((1*3+dx)*64 + n)*128 + kc*2;
                    bh0[nb] = *(const uint32_t*)(smem + CB_O + SWZ(bo0));
                    bh1[nb] = *(const uint32_t*)(smem + CB_O + SWZ(bo0 + 16));
                    bl0[nb] = *(const uint32_t*)(smem + CB_O + SWZ(bo1));
                    bl1[nb] = *(const uint32_t*)(smem + CB_O + SWZ(bo1 + 16));
                }
                #pragma unroll
                for (int m2 = 0; m2 < 2; m2++){
                    int ar  = dy*66 + mq*32 + m2*16 + grp + dx;
                    int ao  = ar*128 + kc*2;
                    int ao8 = (ar+8)*128 + kc*2;
                    uint32_t ah[4], al[4];
                    ah[0] = *(const uint32_t*)(smem + CA_H + SWZ(ao));
                    ah[1] = *(const uint32_t*)(smem + CA_H + SWZ(ao8));
                    ah[2] = *(const uint32_t*)(smem + CA_H + SWZ(ao + 16));
                    ah[3] = *(const uint32_t*)(smem + CA_H + SWZ(ao8 + 16));
                    al[0] = *(const uint32_t*)(smem + CA_L + SWZ(ao));
                    al[1] = *(const uint32_t*)(smem + CA_L + SWZ(ao8));
                    al[2] = *(const uint32_t*)(smem + CA_L + SWZ(ao + 16));
                    al[3] = *(const uint32_t*)(smem + CA_L + SWZ(ao8 + 16));
                    #pragma unroll
                    for (int nb = 0; nb < 4; nb++){
                        mma_bf16(c[m2][nb], ah, bh0[nb], bh1[nb]);
                        mma_bf16(c[m2][nb], ah, bl0[nb], bl1[nb]);
                        mma_bf16(c[m2][nb], al, bh0[nb], bh1[nb]);
                    }
                }
            }
        }
        __syncthreads();
    }

    // ---- cross-K reduce via smem (reuse A region) ----
    __syncthreads();
    float* red = (float*)(smem + CA_H);
    int t = wid & 3;
    if (ks == 1){
        #pragma unroll
        for (int m2 = 0; m2 < 2; m2++)
            #pragma unroll
            for (int nb = 0; nb < 4; nb++)
                #pragma unroll
                for (int j = 0; j < 4; j++){
                    int row = m2*16 + grp + ((j >> 1) << 3);
                    int col = nb*8 + t2 + (j & 1);
                    red[t*1056 + row*33 + col] = c[m2][nb][j];
                }
    }
    __syncthreads();
    if (ks == 0){
        #pragma unroll
        for (int m2 = 0; m2 < 2; m2++)
            #pragma unroll
            for (int nb = 0; nb < 4; nb++)
                #pragma unroll
                for (int j = 0; j < 4; j++){
                    int row = m2*16 + grp + ((j >> 1) << 3);
                    int col = nb*8 + t2 + (j & 1);
                    c[m2][nb][j] += red[t*1056 + row*33 + col];
                }

        float bias[8];
        #pragma unroll
        for (int nb = 0; nb < 4; nb++){
            int oc = nh*32 + nb*8 + t2;
            bias[nb*2+0] = g_bm[layer*CC + oc];
            bias[nb*2+1] = g_bm[layer*CC + oc + 1];
        }
        float* out = selbuf(outsel) + ((size_t)(b*CC) << 16);
        #pragma unroll
        for (int m2 = 0; m2 < 2; m2++){
            #pragma unroll
            for (int jh = 0; jh < 2; jh++){
                int m  = mq*32 + m2*16 + grp + jh*8;
                int wc = w0 + m;
                float c1 = g_tc[wc], s1 = g_ts[wc];
                float acc[8];
                #pragma unroll
                for (int nb = 0; nb < 4; nb++){
                    int oc = nh*32 + nb*8 + t2;
                    acc[nb*2+0] = sz[oc*20].x;
                    acc[nb*2+1] = sz[(oc+1)*20].x;
                }
                float cr = c1, ci = s1;
                for (int ky = 1; ky < 20; ky++){
                    #pragma unroll
                    for (int nb = 0; nb < 4; nb++){
                        int oc = nh*32 + nb*8 + t2;
                        float2 z0 = sz[oc*20 + ky];
                        float2 z1 = sz[(oc+1)*20 + ky];
                        acc[nb*2+0] += 2.f*(z0.x*cr - z0.y*ci);
                        acc[nb*2+1] += 2.f*(z1.x*cr - z1.y*ci);
                    }
                    float nr = cr*c1 - ci*s1;
                    ci = cr*s1 + ci*c1;
                    cr = nr;
                }
                #pragma unroll
                for (int nb = 0; nb < 4; nb++){
                    int oc = nh*32 + nb*8 + t2;
                    #pragma unroll
                    for (int j2 = 0; j2 < 2; j2++){
                        float v = c[m2][nb][jh*2 + j2] + bias[nb*2+j2] + acc[nb*2+j2]*(1.0f/256.0f);
                        if (dogelu) v = gelu_exact(v);
                        out[((size_t)(oc + j2) << 16) + h*WW + wc] = v;
                    }
                }
            }
        }
    }
}

// ======== head via mma: fc1(64->128) GEMM + gelu + fc2 dot ========
__global__ void __launch_bounds__(512) k_fc_mma(const float* __restrict__ b1,
        const float* __restrict__ w2, const float* __restrict__ b2,
        float* __restrict__ out, int sel){
    extern __shared__ unsigned char smem[];
    __nv_bfloat16* sAh = (__nv_bfloat16*)(smem + FA_H);
    __nv_bfloat16* sAl = (__nv_bfloat16*)(smem + FA_L);
    __nv_bfloat16* sBh = (__nv_bfloat16*)(smem + FB_H);
    __nv_bfloat16* sBl = (__nv_bfloat16*)(smem + FB_L);
    float* sb1  = (float*)(smem + FB1);
    float* sw2  = (float*)(smem + FW2);
    float* part = (float*)(smem + FPART);

    int tid = threadIdx.x, wid = tid >> 5, lane = tid & 31;
    int grp = lane >> 2, t2 = (lane & 3) * 2;
    int pbase = blockIdx.x * 128;
    int b  = pbase >> 16;
    int hw0 = pbase & 65535;
    const float* hbuf = selbuf(sel);

    for (int u = tid; u < 128*32; u += 512){
        int px  = u & 127;
        int icp = u >> 7;
        const float* p = hbuf + (((size_t)(b*CC + 2*icp)) << 16) + hw0 + px;
        float f0 = p[0], f1 = p[1 << 16];
        __nv_bfloat16 h0b = __float2bfloat16(f0), h1b = __float2bfloat16(f1);
        uint32_t hp = (uint32_t)*(unsigned short*)&h0b | ((uint32_t)*(unsigned short*)&h1b << 16);
        uint32_t lp = bfpack(f0 - __bfloat162float(h0b), f1 - __bfloat162float(h1b));
        *(uint32_t*)((unsigned char*)sAh + px*144 + icp*4) = hp;
        *(uint32_t*)((unsigned char*)sAl + px*144 + icp*4) = lp;
    }
    for (int u = tid; u < 2*1024; u += 512){
        int s = u >> 10, r = u & 1023;
        int n = r >> 3, k8 = r & 7;
        uint4 v = *(const uint4*)&g_fc1bf[s][n][k8*8];
        unsigned char* dst = (s ? (unsigned char*)sBl : (unsigned char*)sBh);
        *(uint4*)(dst + n*144 + k8*16) = v;
    }
    if (tid < 128){ sb1[tid] = b1[tid]; sw2[tid] = w2[tid]; }
    __syncthreads();

    int mq = wid & 7;
    int nh = wid >> 3;
    float c[8][4];
    #pragma unroll
    for (int nb = 0; nb < 8; nb++)
        #pragma unroll
        for (int j = 0; j < 4; j++) c[nb][j] = 0.f;

    int arow = mq*16 + grp;
    #pragma unroll
    for (int kk = 0; kk < 4; kk++){
        int kc = kk*16 + t2;
        uint32_t ah[4], al[4];
        ah[0] = *(const uint32_t*)(sAh + arow*ICP + kc);
        ah[1] = *(const uint32_t*)(sAh + (arow+8)*ICP + kc);
        ah[2] = *(const uint32_t*)(sAh + arow*ICP + kc + 8);
        ah[3] = *(const uint32_t*)(sAh + (arow+8)*ICP + kc + 8);
        al[0] = *(const uint32_t*)(sAl + arow*ICP + kc);
        al[1] = *(const uint32_t*)(sAl + (arow+8)*ICP + kc);
        al[2] = *(const uint32_t*)(sAl + arow*ICP + kc + 8);
        al[3] = *(const uint32_t*)(sAl + (arow+8)*ICP + kc + 8);
        #pragma unroll
        for (int nb = 0; nb < 8; nb++){
            int n = nh*64 + nb*8 + grp;
            uint32_t bh0 = *(const uint32_t*)(sBh + n*ICP + kc);
            uint32_t bh1 = *(const uint32_t*)(sBh + n*ICP + kc + 8);
            uint32_t bl0 = *(const uint32_t*)(sBl + n*ICP + kc);
            uint32_t bl1 = *(const uint32_t*)(sBl + n*ICP + kc + 8);
            mma_bf16(c[nb], ah, bh0, bh1);
            mma_bf16(c[nb], ah, bl0, bl1);
            mma_bf16(c[nb], al, bh0, bh1);
        }
    }

    float s0 = 0.f, s1 = 0.f;
    #pragma unroll
    for (int nb = 0; nb < 8; nb++){
        int n0 = nh*64 + nb*8 + t2;
        float b10 = sb1[n0], b11 = sb1[n0+1];
        float w20 = sw2[n0], w21 = sw2[n0+1];
        s0 += gelu_exact(c[nb][0] + b10) * w20 + gelu_exact(c[nb][1] + b11) * w21;
        s1 += gelu_exact(c[nb][2] + b10) * w20 + gelu_exact(c[nb][3] + b11) * w21;
    }
    #pragma unroll
    for (int off = 1; off <= 2; off <<= 1){
        s0 += __shfl_xor_sync(0xffffffffu, s0, off);
        s1 += __shfl_xor_sync(0xffffffffu, s1, off);
    }
    if ((lane & 3) == 0){
        part[nh*128 + mq*16 + grp]     = s0;
        part[nh*128 + mq*16 + grp + 8] = s1;
    }
    __syncthreads();
    if (tid < 128) out[pbase + tid] = part[tid] + part[128 + tid] + b2[0];
}

// ---------------- launch ----------------
extern "C" void kernel_launch(void* const* d_in, const int* in_sizes, int n_in,
                              void* d_out, int out_size){
    const float* x     = (const float*)d_in[0];
    const float* fc0_w = (const float*)d_in[1];
    const float* fc0_b = (const float*)d_in[2];
    const float* w1    = (const float*)d_in[3];
    const float* w2    = (const float*)d_in[4];
    const float* chw   = (const float*)d_in[5];
    const float* chb   = (const float*)d_in[6];
    const float* cww   = (const float*)d_in[7];
    const float* cwb   = (const float*)d_in[8];
    const float* pww   = (const float*)d_in[9];
    const float* pwb   = (const float*)d_in[10];
    const float* fc1_w = (const float*)d_in[11];
    const float* fc1_b = (const float*)d_in[12];
    const float* fc2_w = (const float*)d_in[13];
    const float* fc2_b = (const float*)d_in[14];
    float* out = (float*)d_out;

    cudaFuncSetAttribute(k_conv_mma, cudaFuncAttributeMaxDynamicSharedMemorySize, SMEM_CONV);
    cudaFuncSetAttribute(k_dftw_mma, cudaFuncAttributeMaxDynamicSharedMemorySize, DW_SMEM);
    cudaFuncSetAttribute(k_fc_mma,   cudaFuncAttributeMaxDynamicSharedMemorySize, SMEM_FC);

    k_init_tw<<<1, 256>>>();
    k_merge<<<(NL*9*64*64 + 255)/256, 256>>>(chw, cww, pww, chb, cwb, pwb);
    k_wprep<<<(int)(((size_t)NL*800*4096 + 255)/256), 256>>>(w1, w2);
    k_wprep_fc<<<(128*64 + 255)/256, 256>>>(fc1_w);
    k_fc0<<<NPIX/256, 256>>>(x, fc0_w, fc0_b);

    int cur = 0;
    for (int l = 0; l < NL; l++){
        int nxt = cur ^ 1;
        k_dftw_mma<<<1024, 256, DW_SMEM>>>(cur);
        k_dfth <<<dim3(CC, BB), 800>>>();
        k_mix  <<<800, 512>>>(l);
        k_idfth<<<dim3(CC, BB), 256>>>();
        k_conv_mma<<<dim3(4, HH, BB), 256, SMEM_CONV>>>(cur, nxt, l, (l < NL-1) ? 1 : 0);
        cur = nxt;
    }
    k_fc_mma<<<NPIX/128, 512, SMEM_FC>>>(fc1_b, fc2_w, fc2_b, out, cur);
}

// round 17
// speedup vs baseline: 1.6590x; 1.1024x over previous
#include <cuda_runtime.h>
#include <cuda_bf16.h>
#include <cuda_fp16.h>
#include <math.h>
#include <stdint.h>

#define BB 8
#define CC 64
#define HH 256
#define WW 256
#define M1 20
#define M2 20
#define NL 4
#define HW 65536
#define NPIX (BB*HH*WW)

// ---------------- static device scratch ----------------
__device__ float  g_bufA[BB*CC*HW];
__device__ float  g_bufB[BB*CC*HW];
__device__ float2 g_yw [BB*CC*HH*M2];
__device__ float2 g_xft[BB*CC*2*M1*M2];
__device__ float2 g_oft[BB*CC*2*M1*M2];
__device__ float2 g_zh [BB*CC*HH*M2];
__device__ float  g_bm [NL*CC];
__device__ float  g_tc [256];
__device__ float  g_ts [256];
// fp16 conv weights: [l][dy][dx][n*64+ic]
__device__ __align__(16) __half g_wf16[NL][3][3][64*64];
// bf16 hi/lo split DFT-W twiddles: [s][n(48)][k=256]
__device__ __align__(16) __nv_bfloat16 g_Tbf[2][48][256];
// pre-transposed spectral-mix weights: [l][mode][ii*64+o]
__device__ float2 g_wmix[(size_t)NL*800*4096];
// fc1 bf16 hi/lo: [s][n=128][k=64]
__device__ __align__(16) __nv_bfloat16 g_fc1bf[2][128][64];

__device__ __forceinline__ float* selbuf(int s){ return s ? g_bufB : g_bufA; }
__device__ __forceinline__ float gelu_exact(float x){
    return 0.5f * x * (1.0f + erff(x * 0.7071067811865476f));
}
__device__ __forceinline__ uint32_t bfpack(float a, float b){
    __nv_bfloat16 x = __float2bfloat16(a), y = __float2bfloat16(b);
    return (uint32_t)*(unsigned short*)&x | ((uint32_t)*(unsigned short*)&y << 16);
}
__device__ __forceinline__ uint32_t hfpack(float a, float b){
    __half x = __float2half(a), y = __float2half(b);
    return (uint32_t)*(unsigned short*)&x | ((uint32_t)*(unsigned short*)&y << 16);
}
__device__ __forceinline__ void mma_bf16(float* c, const uint32_t* a, uint32_t b0, uint32_t b1){
    asm volatile("mma.sync.aligned.m16n8k16.row.col.f32.bf16.bf16.f32 "
        "{%0,%1,%2,%3}, {%4,%5,%6,%7}, {%8,%9}, {%0,%1,%2,%3};"
        : "+f"(c[0]), "+f"(c[1]), "+f"(c[2]), "+f"(c[3])
        : "r"(a[0]), "r"(a[1]), "r"(a[2]), "r"(a[3]), "r"(b0), "r"(b1));
}
__device__ __forceinline__ void mma_f16(float* c, const uint32_t* a, uint32_t b0, uint32_t b1){
    asm volatile("mma.sync.aligned.m16n8k16.row.col.f32.f16.f16.f32 "
        "{%0,%1,%2,%3}, {%4,%5,%6,%7}, {%8,%9}, {%0,%1,%2,%3};"
        : "+f"(c[0]), "+f"(c[1]), "+f"(c[2]), "+f"(c[3])
        : "r"(a[0]), "r"(a[1]), "r"(a[2]), "r"(a[3]), "r"(b0), "r"(b1));
}
#define SWZ(o) ((o) ^ (((o) >> 3) & 0x70))

// ---- smem layout: conv (fp16 single, 64w x 64oc, swizzled 128B rows) ----
#define CA_O 0                           // fp16 [198 rows][64ic] = 25344 B (reduce buf reuse)
#define CB_O 25344                       // fp16 [192 rows][64ic] = 24576 B
#define CSZ  49920                       // float2 [64][20] = 10240 B
#define SMEM_CONV 60160

// ---- smem layout: k_dftw_mma ----
#define DW_AH 0
#define DW_AL 67584
#define DW_BH 135168
#define DW_BL 160512
#define DW_SMEM 185856

// ---- smem layout: k_fc_mma ----
#define ICP 72
#define FA_H 0
#define FA_L 18432
#define FB_H 36864
#define FB_L 55296
#define FB1  73728
#define FW2  74240
#define FPART 74752
#define SMEM_FC 75776

// ---------------- twiddle init ----------------
__global__ void k_init_tw(){
    int i = threadIdx.x;
    const double TWO_PI = 6.283185307179586476925286766559;
    double th = TWO_PI * (double)i / 256.0;
    g_tc[i] = (float)cos(th);
    g_ts[i] = (float)sin(th);
    for (int n = 0; n < 48; n++){
        float v = 0.f;
        if (n < 20)      v =  (float)cos(TWO_PI * (double)((n*i) & 255) / 256.0);
        else if (n < 40) v = -(float)sin(TWO_PI * (double)(((n-20)*i) & 255) / 256.0);
        __nv_bfloat16 hb = __float2bfloat16(v);
        __nv_bfloat16 lb = __float2bfloat16(v - __bfloat162float(hb));
        g_Tbf[0][n][i] = hb;
        g_Tbf[1][n][i] = lb;
    }
}

// ------- merge convh+convw+pw -> fp16 [l][dy][dx][n][ic] -------
__global__ void k_merge(const float* __restrict__ ch, const float* __restrict__ cw,
                        const float* __restrict__ pw, const float* __restrict__ bh,
                        const float* __restrict__ bw, const float* __restrict__ bp){
    int idx = blockIdx.x * 256 + threadIdx.x;
    const int total = NL*9*64*64;
    if (idx < total){
        int ic = idx & 63;
        int n  = (idx >> 6) & 63;
        int t  = (idx >> 12) % 9;
        int l  = idx / (9*64*64);
        int dy = t / 3, dx = t % 3;
        int src = ((l*CC + n)*CC + ic)*9 + t;
        float v = ch[src] + cw[src];
        if (t == 4) v += pw[(l*CC + n)*CC + ic];
        g_wf16[l][dy][dx][n*64+ic] = __float2half(v);
    }
    if (idx < NL*CC) g_bm[idx] = bh[idx] + bw[idx] + bp[idx];
}

// ------- pre-transpose spectral weights to [l][mode][ii][o] -------
__global__ void k_wprep(const float* __restrict__ w1, const float* __restrict__ w2){
    size_t idx = (size_t)blockIdx.x * 256 + threadIdx.x;
    const size_t total = (size_t)NL*800*4096;
    if (idx >= total) return;
    int o   = idx & 63;
    int ii  = (idx >> 6) & 63;
    int ky  = (int)((idx >> 12) % 20);
    int kxi = (int)((idx / (4096ull*20)) % 40);
    int l   = (int)(idx / (4096ull*800));
    int kxl = (kxi < 20) ? kxi : kxi - 20;
    const float* w = (kxi < 20) ? w1 : w2;
    size_t s = ((((size_t)(l*64 + ii)*64 + o)*20 + kxl)*20 + ky)*2;
    g_wmix[idx] = make_float2(w[s], w[s+1]);
}

// ------- fc1 weights -> bf16 hi/lo [s][n][k] -------
__global__ void k_wprep_fc(const float* __restrict__ fc1_w){
    int idx = blockIdx.x * 256 + threadIdx.x;
    if (idx >= 128*64) return;
    int n = idx >> 6, k = idx & 63;
    float v = fc1_w[k*128 + n];
    __nv_bfloat16 hb = __float2bfloat16(v);
    __nv_bfloat16 lb = __float2bfloat16(v - __bfloat162float(hb));
    g_fc1bf[0][n][k] = hb;
    g_fc1bf[1][n][k] = lb;
}

// ---------------- fc0 lift ----------------
__global__ void k_fc0(const float* __restrict__ x, const float* __restrict__ w,
                      const float* __restrict__ bias){
    __shared__ float sw[3*CC];
    __shared__ float sb[CC];
    int tid = threadIdx.x;
    if (tid < 3*CC) sw[tid] = w[tid];
    if (tid < CC)   sb[tid] = bias[tid];
    __syncthreads();
    int pix = blockIdx.x * 256 + tid;
    int b  = pix >> 16;
    int hw = pix & 65535;
    float x0 = x[pix*3+0], x1 = x[pix*3+1], x2 = x[pix*3+2];
    float* out = selbuf(0);
    #pragma unroll 8
    for (int c = 0; c < CC; c++){
        float v = x0*sw[c] + x1*sw[64+c] + x2*sw[128+c] + sb[c];
        out[((b*CC + c) << 16) + hw] = v;
    }
}

// ============ DFT along W as tensor-core GEMM ============
__global__ void __launch_bounds__(256) k_dftw_mma(int insel){
    extern __shared__ unsigned char smem[];
    __nv_bfloat16* sAh = (__nv_bfloat16*)(smem + DW_AH);
    __nv_bfloat16* sAl = (__nv_bfloat16*)(smem + DW_AL);
    __nv_bfloat16* sBh = (__nv_bfloat16*)(smem + DW_BH);
    __nv_bfloat16* sBl = (__nv_bfloat16*)(smem + DW_BL);
    int tid = threadIdx.x, wid = tid >> 5, lane = tid & 31;
    int grp = lane >> 2, t2 = (lane & 3) * 2;
    int r0 = blockIdx.x * 128;
    const float* X = selbuf(insel) + (size_t)r0 * 256;

    for (int idx = tid; idx < 128*128; idx += 256){
        int r = idx >> 7, k2 = (idx & 127) * 2;
        float2 f = *(const float2*)&X[r*256 + k2];
        __nv_bfloat16 h0 = __float2bfloat16(f.x);
        __nv_bfloat16 h1 = __float2bfloat16(f.y);
        uint32_t hp = (uint32_t)*(unsigned short*)&h0 | ((uint32_t)*(unsigned short*)&h1 << 16);
        uint32_t lp = bfpack(f.x - __bfloat162float(h0), f.y - __bfloat162float(h1));
        *(uint32_t*)((unsigned char*)sAh + (r*264 + k2)*2) = hp;
        *(uint32_t*)((unsigned char*)sAl + (r*264 + k2)*2) = lp;
    }
    for (int idx = tid; idx < 48*128; idx += 256){
        int n = idx / 128, k2 = (idx % 128) * 2;
        *(uint32_t*)((unsigned char*)sBh + (n*264 + k2)*2) = *(const uint32_t*)&g_Tbf[0][n][k2];
        *(uint32_t*)((unsigned char*)sBl + (n*264 + k2)*2) = *(const uint32_t*)&g_Tbf[1][n][k2];
    }
    __syncthreads();

    float c[5][4];
    #pragma unroll
    for (int nb = 0; nb < 5; nb++)
        #pragma unroll
        for (int j = 0; j < 4; j++) c[nb][j] = 0.f;

    int arow = wid*16 + grp;
    #pragma unroll 4
    for (int kk = 0; kk < 16; kk++){
        int kc = kk*16 + t2;
        uint32_t ah[4], al[4];
        ah[0] = *(uint32_t*)((unsigned char*)sAh + (arow*264 + kc)*2);
        ah[1] = *(uint32_t*)((unsigned char*)sAh + ((arow+8)*264 + kc)*2);
        ah[2] = *(uint32_t*)((unsigned char*)sAh + (arow*264 + kc + 8)*2);
        ah[3] = *(uint32_t*)((unsigned char*)sAh + ((arow+8)*264 + kc + 8)*2);
        al[0] = *(uint32_t*)((unsigned char*)sAl + (arow*264 + kc)*2);
        al[1] = *(uint32_t*)((unsigned char*)sAl + ((arow+8)*264 + kc)*2);
        al[2] = *(uint32_t*)((unsigned char*)sAl + (arow*264 + kc + 8)*2);
        al[3] = *(uint32_t*)((unsigned char*)sAl + ((arow+8)*264 + kc + 8)*2);
        #pragma unroll
        for (int nb = 0; nb < 5; nb++){
            int n = nb*8 + grp;
            uint32_t bh0 = *(uint32_t*)((unsigned char*)sBh + (n*264 + kc)*2);
            uint32_t bh1 = *(uint32_t*)((unsigned char*)sBh + (n*264 + kc + 8)*2);
            uint32_t bl0 = *(uint32_t*)((unsigned char*)sBl + (n*264 + kc)*2);
            uint32_t bl1 = *(uint32_t*)((unsigned char*)sBl + (n*264 + kc + 8)*2);
            mma_bf16(c[nb], ah, bh0, bh1);
            mma_bf16(c[nb], ah, bl0, bl1);
            mma_bf16(c[nb], al, bh0, bh1);
        }
    }

    float* yw = (float*)g_yw;
    #pragma unroll
    for (int nb = 0; nb < 5; nb++){
        #pragma unroll
        for (int j = 0; j < 4; j++){
            int n = nb*8 + t2 + (j & 1);
            if (n >= 40) continue;
            int m = wid*16 + grp + ((j >> 1) << 3);
            int col = (n < 20) ? 2*n : 2*(n-20) + 1;
            yw[(size_t)(r0 + m)*40 + col] = c[nb][j];
        }
    }
}

// ---------------- forward DFT along H ----------------
__global__ void k_dfth(){
    __shared__ float2 sy[HH*M2];
    __shared__ float  stc[256], sts[256];
    int tid = threadIdx.x;          // 800
    int c = blockIdx.x, b = blockIdx.y;
    if (tid < 256){ stc[tid] = g_tc[tid]; sts[tid] = g_ts[tid]; }
    const float2* yw = g_yw + (size_t)(b*CC + c)*HH*M2;
    for (int j = tid; j < HH*M2; j += 800) sy[j] = yw[j];
    __syncthreads();
    int kxi = tid / 20, ky = tid % 20;
    int kx  = (kxi < 20) ? kxi : (216 + kxi);
    float re = 0.f, im = 0.f;
    int idx = 0;
    #pragma unroll 4
    for (int h = 0; h < HH; h++){
        float2 y = sy[h*M2 + ky];
        float cth = stc[idx], sth = sts[idx];
        re += y.x*cth + y.y*sth;
        im += y.y*cth - y.x*sth;
        idx = (idx + kx) & 255;
    }
    const float sc = 1.0f/256.0f;
    g_xft[((b*CC + c)*40 + kxi)*M2 + ky] = make_float2(re*sc, im*sc);
}

// ---------------- per-mode complex channel mixing ------------------------------
__global__ void __launch_bounds__(512) k_mix(int layer){
    __shared__ float2 sx[BB*CC];
    __shared__ float  sWr[4096], sWi[4096];
    int tid  = threadIdx.x;
    int mode = blockIdx.x;
    int kxi = mode / 20, ky = mode % 20;
    const float2* wsrc = g_wmix + ((size_t)layer*800 + mode)*4096;
    for (int j = tid; j < 4096; j += 512){
        float2 w = wsrc[j];
        sWr[j] = w.x; sWi[j] = w.y;
    }
    int b = tid >> 6, i = tid & 63;
    sx[tid] = g_xft[((b*CC + i)*40 + kxi)*M2 + ky];
    __syncthreads();
    int o = i;
    float re = 0.f, im = 0.f;
    #pragma unroll 8
    for (int ii = 0; ii < CC; ii++){
        float2 xv = sx[(b << 6) + ii];
        float wr = sWr[ii*64 + o], wi_ = sWi[ii*64 + o];
        re += xv.x*wr - xv.y*wi_;
        im += xv.x*wi_ + xv.y*wr;
    }
    g_oft[((b*CC + o)*40 + kxi)*M2 + ky] = make_float2(re, im);
}

// ---------------- inverse DFT along H (scalar) ------------------------
__global__ void k_idfth(){
    __shared__ float2 so[40*M2];
    __shared__ float  stc[256], sts[256];
    int tid = threadIdx.x;
    int o = blockIdx.x, b = blockIdx.y;
    stc[tid] = g_tc[tid]; sts[tid] = g_ts[tid];
    const float2* op = g_oft + (size_t)(b*CC + o)*40*M2;
    for (int j = tid; j < 800; j += 256) so[j] = op[j];
    __syncthreads();
    int h = tid;
    float2* zout = g_zh + ((size_t)(b*CC + o)*HH + h)*M2;
    for (int ky = 0; ky < M2; ky++){
        float re = 0.f, im = 0.f;
        #pragma unroll
        for (int kxi = 0; kxi < 40; kxi++){
            int kx  = (kxi < 20) ? kxi : (216 + kxi);
            int idx = (h * kx) & 255;
            float2 ov = so[kxi*M2 + ky];
            float cth = stc[idx], sth = sts[idx];
            re += ov.x*cth - ov.y*sth;
            im += ov.x*sth + ov.y*cth;
        }
        zout[ky] = make_float2(re, im);
    }
}

// ======== conv: fp16 single-pass, 64w x 64oc x 256thr, 2 CTAs/SM ====
__global__ void __launch_bounds__(256, 2) k_conv_mma(int insel, int outsel, int layer, int dogelu){
    extern __shared__ unsigned char smem[];
    float2* sz = (float2*)(smem + CSZ);

    int tid = threadIdx.x, wid = tid >> 5, lane = tid & 31;
    int w0 = blockIdx.x * 64;
    int h  = blockIdx.y;
    int b  = blockIdx.z;
    const float* in = selbuf(insel) + ((size_t)(b*CC) << 16);

    // ---- stage A: 3 dy rows x 66 w x 64 ic fp16, w lane-fast ----
    for (int idx = tid; idx < 32*198; idx += 256){
        int icp = idx / 198;            // ic pair 0..31
        int rem = idx % 198;            // dy*66 + wl
        int dy = rem / 66, wl = rem % 66;
        int gh = h + dy - 1;
        int gw = w0 - 1 + wl;
        float f0 = 0.f, f1 = 0.f;
        if (gh >= 0 && gh < HH && gw >= 0 && gw < WW){
            const float* p = in + (((size_t)(2*icp)) << 16) + gh*WW + gw;
            f0 = p[0];
            f1 = p[1 << 16];
        }
        int o = rem*128 + icp*4;
        *(uint32_t*)(smem + CA_O + SWZ(o)) = hfpack(f0, f1);
    }
    for (int idx = tid; idx < 64*20; idx += 256){
        int oc = idx / 20, ky = idx % 20;
        sz[idx] = g_zh[((size_t)(b*CC + oc)*HH + h)*M2 + ky];
    }

    int mq  = wid & 1;               // 32-px half
    int nh  = (wid >> 1) & 1;        // 32-oc half
    int ks  = wid >> 2;              // K half
    int grp = lane >> 2;
    int t2  = (lane & 3) * 2;

    float c[2][4][4];
    #pragma unroll
    for (int m2 = 0; m2 < 2; m2++)
        #pragma unroll
        for (int nb = 0; nb < 4; nb++)
            #pragma unroll
            for (int j = 0; j < 4; j++) c[m2][nb][j] = 0.f;

    for (int dy = 0; dy < 3; dy++){
        int gh = h + dy - 1;
        if (gh < 0 || gh >= HH) continue;
        __syncthreads();
        {   // B stage: 1536 uint4, swizzled 128B rows (192 rows = dx*64+n)
            const uint4* ws = (const uint4*)&g_wf16[layer][dy][0][0];
            for (int u = tid; u < 1536; u += 256){
                int row = u >> 3, k8 = u & 7;
                int o = row*128 + k8*16;
                *(uint4*)(smem + CB_O + SWZ(o)) = ws[u];
            }
        }
        __syncthreads();

        #pragma unroll
        for (int dx = 0; dx < 3; dx++){
            #pragma unroll
            for (int kk2 = 0; kk2 < 2; kk2++){
                int kc = (ks*2 + kk2)*16 + t2;
                uint32_t b0[4], b1[4];
                #pragma unroll
                for (int nb = 0; nb < 4; nb++){
                    int n = nh*32 + nb*8 + grp;
                    int bo = (dx*64 + n)*128 + kc*2;
                    b0[nb] = *(const uint32_t*)(smem + CB_O + SWZ(bo));
                    b1[nb] = *(const uint32_t*)(smem + CB_O + SWZ(bo + 16));
                }
                #pragma unroll
                for (int m2 = 0; m2 < 2; m2++){
                    int ar  = dy*66 + mq*32 + m2*16 + grp + dx;
                    int ao  = ar*128 + kc*2;
                    int ao8 = (ar+8)*128 + kc*2;
                    uint32_t a[4];
                    a[0] = *(const uint32_t*)(smem + CA_O + SWZ(ao));
                    a[1] = *(const uint32_t*)(smem + CA_O + SWZ(ao8));
                    a[2] = *(const uint32_t*)(smem + CA_O + SWZ(ao + 16));
                    a[3] = *(const uint32_t*)(smem + CA_O + SWZ(ao8 + 16));
                    #pragma unroll
                    for (int nb = 0; nb < 4; nb++)
                        mma_f16(c[m2][nb], a, b0[nb], b1[nb]);
                }
            }
        }
        __syncthreads();
    }

    // ---- cross-K reduce via smem (reuse A region; 4*1056*4 = 16896 <= 25344) ----
    __syncthreads();
    float* red = (float*)(smem + CA_O);
    int t = wid & 3;
    if (ks == 1){
        #pragma unroll
        for (int m2 = 0; m2 < 2; m2++)
            #pragma unroll
            for (int nb = 0; nb < 4; nb++)
                #pragma unroll
                for (int j = 0; j < 4; j++){
                    int row = m2*16 + grp + ((j >> 1) << 3);
                    int col = nb*8 + t2 + (j & 1);
                    red[t*1056 + row*33 + col] = c[m2][nb][j];
                }
    }
    __syncthreads();
    if (ks == 0){
        #pragma unroll
        for (int m2 = 0; m2 < 2; m2++)
            #pragma unroll
            for (int nb = 0; nb < 4; nb++)
                #pragma unroll
                for (int j = 0; j < 4; j++){
                    int row = m2*16 + grp + ((j >> 1) << 3);
                    int col = nb*8 + t2 + (j & 1);
                    c[m2][nb][j] += red[t*1056 + row*33 + col];
                }

        float bias[8];
        #pragma unroll
        for (int nb = 0; nb < 4; nb++){
            int oc = nh*32 + nb*8 + t2;
            bias[nb*2+0] = g_bm[layer*CC + oc];
            bias[nb*2+1] = g_bm[layer*CC + oc + 1];
        }
        float* out = selbuf(outsel) + ((size_t)(b*CC) << 16);
        #pragma unroll
        for (int m2 = 0; m2 < 2; m2++){
            #pragma unroll
            for (int jh = 0; jh < 2; jh++){
                int m  = mq*32 + m2*16 + grp + jh*8;
                int wc = w0 + m;
                float c1 = g_tc[wc], s1 = g_ts[wc];
                float acc[8];
                #pragma unroll
                for (int nb = 0; nb < 4; nb++){
                    int oc = nh*32 + nb*8 + t2;
                    acc[nb*2+0] = sz[oc*20].x;
                    acc[nb*2+1] = sz[(oc+1)*20].x;
                }
                float cr = c1, ci = s1;
                for (int ky = 1; ky < 20; ky++){
                    #pragma unroll
                    for (int nb = 0; nb < 4; nb++){
                        int oc = nh*32 + nb*8 + t2;
                        float2 z0 = sz[oc*20 + ky];
                        float2 z1 = sz[(oc+1)*20 + ky];
                        acc[nb*2+0] += 2.f*(z0.x*cr - z0.y*ci);
                        acc[nb*2+1] += 2.f*(z1.x*cr - z1.y*ci);
                    }
                    float nr = cr*c1 - ci*s1;
                    ci = cr*s1 + ci*c1;
                    cr = nr;
                }
                #pragma unroll
                for (int nb = 0; nb < 4; nb++){
                    int oc = nh*32 + nb*8 + t2;
                    #pragma unroll
                    for (int j2 = 0; j2 < 2; j2++){
                        float v = c[m2][nb][jh*2 + j2] + bias[nb*2+j2] + acc[nb*2+j2]*(1.0f/256.0f);
                        if (dogelu) v = gelu_exact(v);
                        out[((size_t)(oc + j2) << 16) + h*WW + wc] = v;
                    }
                }
            }
        }
    }
}

// ======== head via mma: fc1(64->128) GEMM + gelu + fc2 dot ========
__global__ void __launch_bounds__(512) k_fc_mma(const float* __restrict__ b1,
        const float* __restrict__ w2, const float* __restrict__ b2,
        float* __restrict__ out, int sel){
    extern __shared__ unsigned char smem[];
    __nv_bfloat16* sAh = (__nv_bfloat16*)(smem + FA_H);
    __nv_bfloat16* sAl = (__nv_bfloat16*)(smem + FA_L);
    __nv_bfloat16* sBh = (__nv_bfloat16*)(smem + FB_H);
    __nv_bfloat16* sBl = (__nv_bfloat16*)(smem + FB_L);
    float* sb1  = (float*)(smem + FB1);
    float* sw2  = (float*)(smem + FW2);
    float* part = (float*)(smem + FPART);

    int tid = threadIdx.x, wid = tid >> 5, lane = tid & 31;
    int grp = lane >> 2, t2 = (lane & 3) * 2;
    int pbase = blockIdx.x * 128;
    int b  = pbase >> 16;
    int hw0 = pbase & 65535;
    const float* hbuf = selbuf(sel);

    for (int u = tid; u < 128*32; u += 512){
        int px  = u & 127;
        int icp = u >> 7;
        const float* p = hbuf + (((size_t)(b*CC + 2*icp)) << 16) + hw0 + px;
        float f0 = p[0], f1 = p[1 << 16];
        __nv_bfloat16 h0b = __float2bfloat16(f0), h1b = __float2bfloat16(f1);
        uint32_t hp = (uint32_t)*(unsigned short*)&h0b | ((uint32_t)*(unsigned short*)&h1b << 16);
        uint32_t lp = bfpack(f0 - __bfloat162float(h0b), f1 - __bfloat162float(h1b));
        *(uint32_t*)((unsigned char*)sAh + px*144 + icp*4) = hp;
        *(uint32_t*)((unsigned char*)sAl + px*144 + icp*4) = lp;
    }
    for (int u = tid; u < 2*1024; u += 512){
        int s = u >> 10, r = u & 1023;
        int n = r >> 3, k8 = r & 7;
        uint4 v = *(const uint4*)&g_fc1bf[s][n][k8*8];
        unsigned char* dst = (s ? (unsigned char*)sBl : (unsigned char*)sBh);
        *(uint4*)(dst + n*144 + k8*16) = v;
    }
    if (tid < 128){ sb1[tid] = b1[tid]; sw2[tid] = w2[tid]; }
    __syncthreads();

    int mq = wid & 7;
    int nh = wid >> 3;
    float c[8][4];
    #pragma unroll
    for (int nb = 0; nb < 8; nb++)
        #pragma unroll
        for (int j = 0; j < 4; j++) c[nb][j] = 0.f;

    int arow = mq*16 + grp;
    #pragma unroll
    for (int kk = 0; kk < 4; kk++){
        int kc = kk*16 + t2;
        uint32_t ah[4], al[4];
        ah[0] = *(const uint32_t*)(sAh + arow*ICP + kc);
        ah[1] = *(const uint32_t*)(sAh + (arow+8)*ICP + kc);
        ah[2] = *(const uint32_t*)(sAh + arow*ICP + kc + 8);
        ah[3] = *(const uint32_t*)(sAh + (arow+8)*ICP + kc + 8);
        al[0] = *(const uint32_t*)(sAl + arow*ICP + kc);
        al[1] = *(const uint32_t*)(sAl + (arow+8)*ICP + kc);
        al[2] = *(const uint32_t*)(sAl + arow*ICP + kc + 8);
        al[3] = *(const uint32_t*)(sAl + (arow+8)*ICP + kc + 8);
        #pragma unroll
        for (int nb = 0; nb < 8; nb++){
            int n = nh*64 + nb*8 + grp;
            uint32_t bh0 = *(const uint32_t*)(sBh + n*ICP + kc);
            uint32_t bh1 = *(const uint32_t*)(sBh + n*ICP + kc + 8);
            uint32_t bl0 = *(const uint32_t*)(sBl + n*ICP + kc);
            uint32_t bl1 = *(const uint32_t*)(sBl + n*ICP + kc + 8);
            mma_bf16(c[nb], ah, bh0, bh1);
            mma_bf16(c[nb], ah, bl0, bl1);
            mma_bf16(c[nb], al, bh0, bh1);
        }
    }

    float s0 = 0.f, s1 = 0.f;
    #pragma unroll
    for (int nb = 0; nb < 8; nb++){
        int n0 = nh*64 + nb*8 + t2;
        float b10 = sb1[n0], b11 = sb1[n0+1];
        float w20 = sw2[n0], w21 = sw2[n0+1];
        s0 += gelu_exact(c[nb][0] + b10) * w20 + gelu_exact(c[nb][1] + b11) * w21;
        s1 += gelu_exact(c[nb][2] + b10) * w20 + gelu_exact(c[nb][3] + b11) * w21;
    }
    #pragma unroll
    for (int off = 1; off <= 2; off <<= 1){
        s0 += __shfl_xor_sync(0xffffffffu, s0, off);
        s1 += __shfl_xor_sync(0xffffffffu, s1, off);
    }
    if ((lane & 3) == 0){
        part[nh*128 + mq*16 + grp]     = s0;
        part[nh*128 + mq*16 + grp + 8] = s1;
    }
    __syncthreads();
    if (tid < 128) out[pbase + tid] = part[tid] + part[128 + tid] + b2[0];
}

// ---------------- launch ----------------
extern "C" void kernel_launch(void* const* d_in, const int* in_sizes, int n_in,
                              void* d_out, int out_size){
    const float* x     = (const float*)d_in[0];
    const float* fc0_w = (const float*)d_in[1];
    const float* fc0_b = (const float*)d_in[2];
    const float* w1    = (const float*)d_in[3];
    const float* w2    = (const float*)d_in[4];
    const float* chw   = (const float*)d_in[5];
    const float* chb   = (const float*)d_in[6];
    const float* cww   = (const float*)d_in[7];
    const float* cwb   = (const float*)d_in[8];
    const float* pww   = (const float*)d_in[9];
    const float* pwb   = (const float*)d_in[10];
    const float* fc1_w = (const float*)d_in[11];
    const float* fc1_b = (const float*)d_in[12];
    const float* fc2_w = (const float*)d_in[13];
    const float* fc2_b = (const float*)d_in[14];
    float* out = (float*)d_out;

    cudaFuncSetAttribute(k_conv_mma, cudaFuncAttributeMaxDynamicSharedMemorySize, SMEM_CONV);
    cudaFuncSetAttribute(k_dftw_mma, cudaFuncAttributeMaxDynamicSharedMemorySize, DW_SMEM);
    cudaFuncSetAttribute(k_fc_mma,   cudaFuncAttributeMaxDynamicSharedMemorySize, SMEM_FC);

    k_init_tw<<<1, 256>>>();
    k_merge<<<(NL*9*64*64 + 255)/256, 256>>>(chw, cww, pww, chb, cwb, pwb);
    k_wprep<<<(int)(((size_t)NL*800*4096 + 255)/256), 256>>>(w1, w2);
    k_wprep_fc<<<(128*64 + 255)/256, 256>>>(fc1_w);
    k_fc0<<<NPIX/256, 256>>>(x, fc0_w, fc0_b);

    int cur = 0;
    for (int l = 0; l < NL; l++){
        int nxt = cur ^ 1;
        k_dftw_mma<<<1024, 256, DW_SMEM>>>(cur);
        k_dfth <<<dim3(CC, BB), 800>>>();
        k_mix  <<<800, 512>>>(l);
        k_idfth<<<dim3(CC, BB), 256>>>();
        k_conv_mma<<<dim3(4, HH, BB), 256, SMEM_CONV>>>(cur, nxt, l, (l < NL-1) ? 1 : 0);
        cur = nxt;
    }
    k_fc_mma<<<NPIX/128, 512, SMEM_FC>>>(fc1_b, fc2_w, fc2_b, out, cur);
}